// round 17
// baseline (speedup 1.0000x reference)
#include <cuda_runtime.h>
#include <cuda_bf16.h>
#include <math.h>
#include <stdint.h>

// ContrastLoss: feat [4,64,512,512] f32, gt [4,19,512,512] i32 -> scalar f32

#define NPIX   (4 * 262144)
#define HW     262144
#define KCLS   19
#define CCH    64
#define TAUF   0.07f
#define LOG2E  1.4426950408889634f
#define CH64   16384               // NPIX / 64 chunks
#define KPAD   20                  // classes padded to 20 (class 19 = zero)

// -------- device scratch --------
__device__ float    g_k0[KCLS * CCH];
__device__ unsigned g_maskbuf[NPIX];
__device__ int      g_cnt[1024];
__device__ double   g_loss;

// ======== f32x2 helpers ========
__device__ __forceinline__ unsigned long long pack2(float a, float b) {
    unsigned long long r;
    asm("mov.b64 %0, {%1, %2};" : "=l"(r) : "f"(a), "f"(b));
    return r;
}
__device__ __forceinline__ void unpack2(unsigned long long v, float& a, float& b) {
    asm("mov.b64 {%0, %1}, %2;" : "=f"(a), "=f"(b) : "l"(v));
}
__device__ __forceinline__ void ffma2(unsigned long long& d, unsigned long long a,
                                      unsigned long long b) {
    asm("fma.rn.f32x2 %0, %1, %2, %0;" : "+l"(d) : "l"(a), "l"(b));
}

// ======== bf16 hi/lo pack ========
__device__ __forceinline__ uint32_t hilo(float f) {
    uint32_t h;
    asm("cvt.rn.bf16x2.f32 %0, %1, %2;" : "=r"(h) : "f"(0.f), "f"(f));
    const float hf = __uint_as_float(h << 16);
    const float lo = f - hf;
    uint32_t r;
    asm("cvt.rn.bf16x2.f32 %0, %1, %2;" : "=r"(r) : "f"(lo), "f"(f));
    return r;
}

// ======== warp MMA m16n8k16 bf16 ========
__device__ __forceinline__ void mma16816(float* d, uint32_t a0, uint32_t a1,
                                         uint32_t a2, uint32_t a3,
                                         uint32_t b0, uint32_t b1) {
    asm volatile(
        "mma.sync.aligned.m16n8k16.row.col.f32.bf16.bf16.f32 "
        "{%0,%1,%2,%3}, {%4,%5,%6,%7}, {%8,%9}, {%0,%1,%2,%3};"
        : "+f"(d[0]), "+f"(d[1]), "+f"(d[2]), "+f"(d[3])
        : "r"(a0), "r"(a1), "r"(a2), "r"(a3), "r"(b0), "r"(b1));
}

// -------- launch 1: zero accumulators --------
__global__ void k_zero() {
    int t = blockIdx.x * 256 + threadIdx.x;
    if (t < KCLS * CCH) g_k0[t] = 0.f;
    if (t == 0) g_loss = 0.0;
}

// -------- launch 0: build 19-bit pixel masks + per-block pos counts --------
__global__ __launch_bounds__(256) void k_mask(const int* __restrict__ gt) {
    const int p4 = (blockIdx.x * 256 + threadIdx.x) * 4;   // 1024 blocks exactly
    const int b  = p4 >> 18;
    const int hw = p4 & (HW - 1);
    unsigned m0 = 0, m1 = 0, m2 = 0, m3 = 0;
#pragma unroll
    for (int k = 0; k < KCLS; k++) {
        const int4 g = *reinterpret_cast<const int4*>(
            gt + (size_t)(b * KCLS + k) * HW + hw);
        m0 |= (unsigned)(g.x == 1) << k;
        m1 |= (unsigned)(g.y == 1) << k;
        m2 |= (unsigned)(g.z == 1) << k;
        m3 |= (unsigned)(g.w == 1) << k;
    }
    *reinterpret_cast<uint4*>(&g_maskbuf[p4]) = make_uint4(m0, m1, m2, m3);
    int cnt = __popc(m0) + __popc(m1) + __popc(m2) + __popc(m3);
#pragma unroll
    for (int o = 16; o; o >>= 1) cnt += __shfl_xor_sync(0xffffffffu, cnt, o);
    __shared__ int sc[8];
    if ((threadIdx.x & 31) == 0) sc[threadIdx.x >> 5] = cnt;
    __syncthreads();
    if (threadIdx.x == 0) {
        int s = 0;
#pragma unroll
        for (int w = 0; w < 8; w++) s += sc[w];
        g_cnt[blockIdx.x] = s;
    }
}

// -------- launch 2: smem-staged HMMA prototype GEMM (exact R10, 58.7us) --------
__global__ __launch_bounds__(256, 4) void k_proto_mma(const float* __restrict__ feat) {
    __shared__ uint32_t sA[64 * 80];
    __shared__ uint32_t sM[64];
    __shared__ float    sk0[KCLS * CCH];

    const int tid  = threadIdx.x;
    const int w    = tid >> 5;
    const int lane = tid & 31;
    const int g    = lane >> 2;
    const int t    = lane & 3;
    const int chb  = (w & 3) * 16;
    const int hb   = (w >> 2) * 32;
    const int sc_hi = lane >> 4;
    const int sc_px = (lane & 15) * 4;

    for (int i = tid; i < KCLS * CCH; i += 256) sk0[i] = 0.f;

    float d0[4] = {0.f, 0.f, 0.f, 0.f};
    float d1[4] = {0.f, 0.f, 0.f, 0.f};
    float d2[4] = {0.f, 0.f, 0.f, 0.f};

    for (int chunk = blockIdx.x; chunk < CH64; chunk += gridDim.x) {
        const int P  = chunk * 64;
        const int b  = P >> 18;
        const int hw = P & (HW - 1);
        __syncthreads();

#pragma unroll
        for (int i = 0; i < 4; i++) {
            const int ch = w * 8 + 2 * i + sc_hi;
            const float4 f = *reinterpret_cast<const float4*>(
                feat + (size_t)(b * CCH + ch) * HW + hw + sc_px);
            const uint32_t h0 = hilo(f.x);
            const uint32_t h1 = hilo(f.y);
            const uint32_t h2 = hilo(f.z);
            const uint32_t h3 = hilo(f.w);
            const int word = ch * 80 + (sc_px ^ ((ch & 3) << 3));
            *reinterpret_cast<uint4*>(&sA[word]) = make_uint4(h0, h1, h2, h3);
        }
        if (tid < 16)
            *reinterpret_cast<uint4*>(&sM[tid * 4]) =
                *reinterpret_cast<const uint4*>(&g_maskbuf[P + tid * 4]);
        __syncthreads();

#pragma unroll
        for (int s = 0; s < 4; s++) {
            const int px = hb + 8 * s + 2 * t;
            const int sw = px ^ ((g & 3) << 3);
            const uint2 A0 = *reinterpret_cast<const uint2*>(&sA[(chb + g) * 80 + sw]);
            const uint2 A1 = *reinterpret_cast<const uint2*>(&sA[(chb + g + 8) * 80 + sw]);
            const uint2 M  = *reinterpret_cast<const uint2*>(&sM[px]);
            {
                const uint32_t b0 = ((M.x >> g) & 1u) * 0x3F803F80u;
                const uint32_t b1 = ((M.y >> g) & 1u) * 0x3F803F80u;
                mma16816(d0, A0.x, A1.x, A0.y, A1.y, b0, b1);
            }
            {
                const uint32_t b0 = ((M.x >> (8 + g)) & 1u) * 0x3F803F80u;
                const uint32_t b1 = ((M.y >> (8 + g)) & 1u) * 0x3F803F80u;
                mma16816(d1, A0.x, A1.x, A0.y, A1.y, b0, b1);
            }
            {
                const uint32_t b0 = ((M.x >> (16 + g)) & 1u) * 0x3F803F80u;
                const uint32_t b1 = ((M.y >> (16 + g)) & 1u) * 0x3F803F80u;
                mma16816(d2, A0.x, A1.x, A0.y, A1.y, b0, b1);
            }
        }
    }

    __syncthreads();
    {
        const int c0 = chb + g;
        const int c1 = chb + g + 8;
        const int k0c = 2 * t, k1c = 2 * t + 1;
        atomicAdd(&sk0[(k0c)     * CCH + c0], d0[0]);
        atomicAdd(&sk0[(k1c)     * CCH + c0], d0[1]);
        atomicAdd(&sk0[(k0c)     * CCH + c1], d0[2]);
        atomicAdd(&sk0[(k1c)     * CCH + c1], d0[3]);
        atomicAdd(&sk0[(8 + k0c) * CCH + c0], d1[0]);
        atomicAdd(&sk0[(8 + k1c) * CCH + c0], d1[1]);
        atomicAdd(&sk0[(8 + k0c) * CCH + c1], d1[2]);
        atomicAdd(&sk0[(8 + k1c) * CCH + c1], d1[3]);
        if (16 + k0c < KCLS) {
            atomicAdd(&sk0[(16 + k0c) * CCH + c0], d2[0]);
            atomicAdd(&sk0[(16 + k0c) * CCH + c1], d2[2]);
        }
        if (16 + k1c < KCLS) {
            atomicAdd(&sk0[(16 + k1c) * CCH + c0], d2[1]);
            atomicAdd(&sk0[(16 + k1c) * CCH + c1], d2[3]);
        }
    }
    __syncthreads();
    for (int i = tid; i < KCLS * CCH; i += 256) atomicAdd(&g_k0[i], sk0[i]);
}

// -------- pair softmax/NLL: classes split across thread pair, merged by shfl ---
// Each thread holds 10 scaled logits (pad class forced to -inf). Both pair
// threads return the identical full-pixel loss; caller adds from even only.
__device__ __forceinline__ float pair_loss(const float* __restrict__ l,
                                           float ssum, unsigned m,
                                           int kb, int h) {
    const float sc = 1.f / fmaxf(sqrtf(ssum), 1e-12f);
    float v[10];
    float mx = -1e30f;
#pragma unroll
    for (int k = 0; k < 10; k++) v[k] = l[k] * sc;
    if (h) v[9] = -1e30f;                       // pad class 19
#pragma unroll
    for (int k = 0; k < 10; k++) mx = fmaxf(mx, v[k]);
    mx = fmaxf(mx, __shfl_xor_sync(0xffffffffu, mx, 1));
    float se = 0.f, sl = 0.f;
#pragma unroll
    for (int k = 0; k < 10; k++) {
        se += exp2f((v[k] - mx) * LOG2E);       // pad -> exp2(-huge) = 0
        if ((m >> (kb + k)) & 1u) sl += v[k];   // bit 19 never set
    }
    se += __shfl_xor_sync(0xffffffffu, se, 1);
    sl += __shfl_xor_sync(0xffffffffu, sl, 1);
    return (float)__popc(m) * (mx + logf(se)) - sl;
}

// -------- launch 3: fp32 logits + softmax NLL, class-split pairs (PROFILED) ----
// Pair (2i, 2i+1) shares 4 pixels: even thread classes 0..9, odd 10..19(pad).
// Feat loads are pair-identical (warp broadcast, traffic unchanged); LDS and
// accumulator registers halve -> launch_bounds(256,3), 24 warps/SM.
__global__ __launch_bounds__(256, 3) void k_loss(const float* __restrict__ feat) {
    __shared__ unsigned long long sknd[KPAD * CCH];   // (kn/tau, kn/tau), class 19 = 0
    __shared__ float sinv[KCLS];
    if (threadIdx.x < KCLS) {
        float s = 0.f;
#pragma unroll
        for (int c = 0; c < CCH; c++) {
            const float v = g_k0[threadIdx.x * CCH + c];
            s = fmaf(v, v, s);
        }
        sinv[threadIdx.x] = 1.f / (fmaxf(sqrtf(s), 1e-12f) * TAUF);
    }
    __syncthreads();
    for (int t = threadIdx.x; t < KPAD * CCH; t += 256) {
        const int k = t >> 6;
        const float v = (k < KCLS) ? g_k0[k * CCH + (t & 63)] * sinv[k] : 0.f;
        sknd[t] = pack2(v, v);
    }
    __syncthreads();

    const int tid = threadIdx.x;
    const int h   = tid & 1;                    // class half
    const int kb  = h * 10;
    const int p4  = (blockIdx.x * 128 + (tid >> 1)) * 4;   // 2048 blocks exactly
    const uint4 m  = *reinterpret_cast<const uint4*>(&g_maskbuf[p4]);
    const int   b  = p4 >> 18;
    const int   hw = p4 & (HW - 1);
    const float* fb = feat + (size_t)(b * CCH) * HW + hw;

    unsigned long long acca[10], accb[10];
#pragma unroll
    for (int k = 0; k < 10; k++) { acca[k] = 0ull; accb[k] = 0ull; }
    unsigned long long ssa = 0ull, ssb = 0ull;

#pragma unroll 2
    for (int c4 = 0; c4 < 16; c4++) {
        const float4 f0 = *reinterpret_cast<const float4*>(fb + (size_t)(4 * c4 + 0) * HW);
        const float4 f1 = *reinterpret_cast<const float4*>(fb + (size_t)(4 * c4 + 1) * HW);
        const float4 f2 = *reinterpret_cast<const float4*>(fb + (size_t)(4 * c4 + 2) * HW);
        const float4 f3 = *reinterpret_cast<const float4*>(fb + (size_t)(4 * c4 + 3) * HW);
        const unsigned long long A0 = pack2(f0.x, f0.y), B0 = pack2(f0.z, f0.w);
        const unsigned long long A1 = pack2(f1.x, f1.y), B1 = pack2(f1.z, f1.w);
        const unsigned long long A2 = pack2(f2.x, f2.y), B2 = pack2(f2.z, f2.w);
        const unsigned long long A3 = pack2(f3.x, f3.y), B3 = pack2(f3.z, f3.w);
        ffma2(ssa, A0, A0); ffma2(ssb, B0, B0);
        ffma2(ssa, A1, A1); ffma2(ssb, B1, B1);
        ffma2(ssa, A2, A2); ffma2(ssb, B2, B2);
        ffma2(ssa, A3, A3); ffma2(ssb, B3, B3);
#pragma unroll
        for (int k = 0; k < 10; k++) {
            const ulonglong2 k01 =
                *reinterpret_cast<const ulonglong2*>(&sknd[(kb + k) * CCH + 4 * c4]);
            const ulonglong2 k23 =
                *reinterpret_cast<const ulonglong2*>(&sknd[(kb + k) * CCH + 4 * c4 + 2]);
            ffma2(acca[k], A0, k01.x); ffma2(accb[k], B0, k01.x);
            ffma2(acca[k], A1, k01.y); ffma2(accb[k], B1, k01.y);
            ffma2(acca[k], A2, k23.x); ffma2(accb[k], B2, k23.x);
            ffma2(acca[k], A3, k23.y); ffma2(accb[k], B3, k23.y);
        }
    }

    float s0, s1, s2, s3;
    unpack2(ssa, s0, s1);
    unpack2(ssb, s2, s3);
    float l0[10], l1[10], l2[10], l3[10];
#pragma unroll
    for (int k = 0; k < 10; k++) {
        unpack2(acca[k], l0[k], l1[k]);
        unpack2(accb[k], l2[k], l3[k]);
    }
    float lsum = 0.f;
    {
        const float t0 = pair_loss(l0, s0, m.x, kb, h);
        const float t1 = pair_loss(l1, s1, m.y, kb, h);
        const float t2 = pair_loss(l2, s2, m.z, kb, h);
        const float t3 = pair_loss(l3, s3, m.w, kb, h);
        if (h == 0) lsum = t0 + t1 + t2 + t3;   // identical on both; add once
    }

    // block reduction -> double atomic
#pragma unroll
    for (int o = 16; o; o >>= 1) lsum += __shfl_xor_sync(0xffffffffu, lsum, o);
    __shared__ float wsum[8];
    if ((threadIdx.x & 31) == 0) wsum[threadIdx.x >> 5] = lsum;
    __syncthreads();
    if (threadIdx.x < 8) {
        float v = wsum[threadIdx.x];
#pragma unroll
        for (int o = 4; o; o >>= 1) v += __shfl_xor_sync(0x000000ffu, v, o);
        if (threadIdx.x == 0) atomicAdd(&g_loss, (double)v);
    }
}

// -------- launch 4: finalize --------
__global__ void k_fin(float* out) {
    int s = 0;
    for (int t = threadIdx.x; t < 1024; t += 256) s += g_cnt[t];
#pragma unroll
    for (int o = 16; o; o >>= 1) s += __shfl_xor_sync(0xffffffffu, s, o);
    __shared__ int ws[8];
    if ((threadIdx.x & 31) == 0) ws[threadIdx.x >> 5] = s;
    __syncthreads();
    if (threadIdx.x == 0) {
        int np = 0;
#pragma unroll
        for (int w = 0; w < 8; w++) np += ws[w];
        out[0] = (float)(g_loss / (double)(np > 0 ? np : 1));
    }
}

extern "C" void kernel_launch(void* const* d_in, const int* in_sizes, int n_in,
                              void* d_out, int out_size) {
    const float* feat = (const float*)d_in[0];
    const int*   gt   = (const int*)d_in[1];
    float*       out  = (float*)d_out;

    k_mask     <<<NPIX / (256 * 4), 256>>>(gt);
    k_zero     <<<5, 256>>>();
    k_proto_mma<<<592, 256>>>(feat);
    k_loss     <<<NPIX / (128 * 4), 256>>>(feat);
    k_fin      <<<1, 256>>>(out);
}